// round 14
// baseline (speedup 1.0000x reference)
#include <cuda_runtime.h>
#include <cuda_fp16.h>
#include <cstdint>
#include <math.h>

#define BB 8
#define SS 4096
#define DD 1024
#define NN 64
#define SHIFT 2048
#define NCH 128
#define CHL 32
#define TILE_C 32

// ---------------- scratch (device globals) ----------------
__device__ float g_wT[DD * 128];            // [d][o]: o=2n -> lnw*kw, o=2n+1 -> lnw*vw
__device__ float g_wsum[128];
__device__ float g_lbsum[128];
__device__ float g_gate[DD];
__device__ float g_w[NN];                   // exp(time_decay)
__device__ float g_exptf[NN];               // exp(time_first)
__device__ float4 g_owQ[16 * DD];           // [n4][d] = ow[d][4n4..4n4+3]
__device__ uint2 g_bfragH[16 * 2048];       // frag-major fp16 weights: [ch][k16][n8][lane] = (b0,b1)
__device__ float g_wkv[BB * SS * NN];
__device__ float g_chunk[BB * NCH * NN];
__device__ float g_carry[BB * NCH * NN];

// ---------------- packed fp32x2 FMA ----------------
__device__ __forceinline__ float2 ffma2(float2 a, float2 b, float2 c) {
    float2 d;
    asm("fma.rn.f32x2 %0, %1, %2, %3;"
        : "=l"(*reinterpret_cast<unsigned long long*>(&d))
        : "l"(*reinterpret_cast<unsigned long long*>(&a)),
          "l"(*reinterpret_cast<unsigned long long*>(&b)),
          "l"(*reinterpret_cast<unsigned long long*>(&c)));
    return d;
}

// ---------------- HMMA helpers (sm_80+ baseline) ----------------
__device__ __forceinline__ void mma_f16(float* c, const unsigned* a, unsigned b0, unsigned b1) {
    asm volatile("mma.sync.aligned.m16n8k16.row.col.f32.f16.f16.f32 "
                 "{%0,%1,%2,%3}, {%4,%5,%6,%7}, {%8,%9}, {%0,%1,%2,%3};"
                 : "+f"(c[0]), "+f"(c[1]), "+f"(c[2]), "+f"(c[3])
                 : "r"(a[0]), "r"(a[1]), "r"(a[2]), "r"(a[3]), "r"(b0), "r"(b1));
}
__device__ __forceinline__ void ldm4(unsigned* r, unsigned addr) {
    asm volatile("ldmatrix.sync.aligned.m8n8.x4.shared.b16 {%0,%1,%2,%3}, [%4];"
                 : "=r"(r[0]), "=r"(r[1]), "=r"(r[2]), "=r"(r[3]) : "r"(addr));
}
__device__ __forceinline__ unsigned packh(float a, float b) {
    __half2 t = __floats2half2_rn(a, b);
    return *reinterpret_cast<unsigned*>(&t);
}
__device__ __forceinline__ float h2f(float a) {
    return __half2float(__float2half_rn(a));
}

// ---------------- prep kernels ----------------
__global__ void prep_a(const float* __restrict__ kw, const float* __restrict__ vw,
                       const float* __restrict__ lnw, const float* __restrict__ tsg,
                       const float* __restrict__ td, const float* __restrict__ tf) {
    int idx = blockIdx.x * 256 + threadIdx.x;
    int d = idx >> 7;
    int o = idx & 127;
    int n = o >> 1;
    const float* src = (o & 1) ? vw : kw;
    g_wT[idx] = lnw[d] * src[n * DD + d];
    if (o == 0) g_gate[d] = 1.f / (1.f + expf(-tsg[d]));
    if (idx < NN) g_w[idx] = expf(td[idx]);
    else if (idx < 2 * NN) g_exptf[idx - NN] = expf(tf[idx - NN]);
}

// fp16 fragment-major weight pack + ow transpose
__global__ void prep_bfrag(const float* __restrict__ ow) {
    int idx = blockIdx.x * 256 + threadIdx.x;   // 0..32767
    int lane = idx & 31;
    int n8 = (idx >> 5) & 15;
    int s = (idx >> 9) & 3;
    int ch = idx >> 11;
    int o = n8 * 8 + (lane >> 2);
    int kb = ch * 64 + s * 16 + (lane & 3) * 2;
    float w0 = g_wT[(size_t)kb * 128 + o];
    float w1 = g_wT[(size_t)(kb + 1) * 128 + o];
    float w8 = g_wT[(size_t)(kb + 8) * 128 + o];
    float w9 = g_wT[(size_t)(kb + 9) * 128 + o];
    g_bfragH[idx] = make_uint2(packh(w0, w1), packh(w8, w9));
    if (idx < 16384) {
        int d = idx & (DD - 1);
        int n4 = idx >> 10;
        g_owQ[idx] = *reinterpret_cast<const float4*>(&ow[d * NN + 4 * n4]);
    }
}

__global__ void prep_b(const float* __restrict__ kw, const float* __restrict__ vw,
                       const float* __restrict__ lnb) {
    __shared__ float red[2][8];
    int o = blockIdx.x;
    int n = o >> 1;
    const float* src = (o & 1) ? vw : kw;
    int tid = threadIdx.x;
    float ws = 0.f, lb = 0.f;
    for (int d = tid; d < DD; d += 256) {
        ws += g_wT[d * 128 + o];
        lb += lnb[d] * src[n * DD + d];
    }
#pragma unroll
    for (int off = 16; off; off >>= 1) {
        ws += __shfl_xor_sync(0xffffffffu, ws, off);
        lb += __shfl_xor_sync(0xffffffffu, lb, off);
    }
    if ((tid & 31) == 0) { red[0][tid >> 5] = ws; red[1][tid >> 5] = lb; }
    __syncthreads();
    if (tid == 0) {
        float a = 0.f, c = 0.f;
#pragma unroll
        for (int i = 0; i < 8; i++) { a += red[0][i]; c += red[1][i]; }
        g_wsum[o] = a;
        g_lbsum[o] = c;
    }
}

// ---------------- kernel A: HMMA fp16-split KV projection (2-D warp split) ----------------
// grid 256 (8 b x 32 tiles of 128 rows), 256 threads, occ 2.
// warp = (wg = warp>>1 rows 32wg..+31, jg = warp&1 col-half).
// B fragments read directly from L2 via __ldg (no smem staging).
// smem: Ah 0..18432 | Al 18432..36864 | consts to 39168
#define SM_AH 0
#define SM_AL 18432
#define SM_MU 36864
#define SM_INV 37376
#define SM_WS 37888
#define SM_LB 38400
#define SM_ETF 38912
#define SMEM_A_BYTES 39168

__global__ void __launch_bounds__(256, 2)
kernelA(const float* __restrict__ x) {
    extern __shared__ char smc[];
    unsigned sbase = (unsigned)__cvta_generic_to_shared(smc);

    int b = blockIdx.x >> 5;
    int tp = blockIdx.x & 31;
    int t0 = tp * 128;
    int tid = threadIdx.x;
    int lane = tid & 31;
    int warp = tid >> 5;
    int wg = warp >> 1;                 // row group (32 rows)
    int jg = warp & 1;                  // col half (8 n8 tiles)
    int R0 = wg * 32;
    int row = tid >> 1;                 // staging row 0..127
    int khalf = (tid & 1) * 32;         // float offset within 64-d chunk

    float* mu_s  = reinterpret_cast<float*>(smc + SM_MU);
    float* inv_s = reinterpret_cast<float*>(smc + SM_INV);
    float* ws_s  = reinterpret_cast<float*>(smc + SM_WS);
    float* lb_s  = reinterpret_cast<float*>(smc + SM_LB);
    float* etf_s = reinterpret_cast<float*>(smc + SM_ETF);
    if (tid < 128) {
        ws_s[tid] = g_wsum[tid];
        lb_s[tid] = g_lbsum[tid];
        if (tid < 64) etf_s[tid] = g_exptf[tid];
    }

    const float4* xt4 = reinterpret_cast<const float4*>(x + ((size_t)(b * SS) + t0 + row) * DD);
    const float4* xc4 = reinterpret_cast<const float4*>(x + ((size_t)(b * SS) + ((t0 + row) ^ SHIFT)) * DD);
    const float4* g4 = reinterpret_cast<const float4*>(g_gate);

    float ssum = 0.f, ssq = 0.f;
    float acc[2][8][4];
#pragma unroll
    for (int i = 0; i < 2; i++)
#pragma unroll
        for (int j = 0; j < 8; j++)
#pragma unroll
            for (int c = 0; c < 4; c++) acc[i][j][c] = 0.f;

    char* ah = smc + SM_AH;
    char* al = smc + SM_AL;

#pragma unroll 1
    for (int ch = 0; ch < 16; ch++) {
        __syncthreads();   // previous compute done; safe to overwrite tiles
        // ---- stage A: blend + stats + fp16 hi/lo split ----
#pragma unroll
        for (int i = 0; i < 8; i++) {
            int f4i = ch * 16 + (tid & 1) * 8 + i;
            float4 xv = xt4[f4i];
            float4 xc = xc4[f4i];
            float4 g = __ldg(&g4[f4i]);
            float s0 = xv.x + g.x * (xc.x - xv.x);
            float s1 = xv.y + g.y * (xc.y - xv.y);
            float s2 = xv.z + g.z * (xc.z - xv.z);
            float s3 = xv.w + g.w * (xc.w - xv.w);
            ssum += s0 + s1 + s2 + s3;
            ssq  += s0 * s0 + s1 * s1 + s2 * s2 + s3 * s3;
            float h0 = h2f(s0), h1 = h2f(s1), h2 = h2f(s2), h3 = h2f(s3);
            int klocal = khalf + i * 4;
            *reinterpret_cast<uint2*>(ah + row * 144 + klocal * 2) =
                make_uint2(packh(h0, h1), packh(h2, h3));
            *reinterpret_cast<uint2*>(al + row * 144 + klocal * 2) =
                make_uint2(packh(s0 - h0, s1 - h1), packh(s2 - h2, s3 - h3));
        }
        __syncthreads();

        // ---- compute: 4 k16 x (2 m16 x 8 n8) x 2 split-MMAs; B from L2 ----
        const uint2* bgl = &g_bfragH[ch * 2048 + (jg * 8) * 32 + lane];
#pragma unroll
        for (int k16 = 0; k16 < 4; k16++) {
            unsigned kofs = (unsigned)((k16 * 16 + ((lane & 16) ? 8 : 0)) * 2);
            unsigned a_h[2][4], a_l[2][4];
#pragma unroll
            for (int i = 0; i < 2; i++) {
                unsigned aoff = (unsigned)((R0 + i * 16 + (lane & 15)) * 144) + kofs;
                ldm4(a_h[i], sbase + SM_AH + aoff);
                ldm4(a_l[i], sbase + SM_AL + aoff);
            }
#pragma unroll
            for (int j = 0; j < 8; j++) {
                uint2 B = __ldg(&bgl[(k16 * 16 + j) * 32]);
                mma_f16(acc[0][j], a_h[0], B.x, B.y);
                mma_f16(acc[0][j], a_l[0], B.x, B.y);
                mma_f16(acc[1][j], a_h[1], B.x, B.y);
                mma_f16(acc[1][j], a_l[1], B.x, B.y);
            }
        }
    }

    // ---- LN stats finalize (tid pairs share a row) ----
    ssum += __shfl_xor_sync(0xffffffffu, ssum, 1);
    ssq  += __shfl_xor_sync(0xffffffffu, ssq, 1);
    if ((tid & 1) == 0) {
        float mu = ssum * (1.f / DD);
        float var = ssq * (1.f / DD) - mu * mu;
        mu_s[row] = mu;
        inv_s[row] = rsqrtf(var + 1e-5f);
    }
    __syncthreads();

    // ---- epilogue: LN fold + wkv -> smem (overlay A region, pitch 68) ----
    float* wkv_s = reinterpret_cast<float*>(smc);
    int tr = lane >> 2, tc = lane & 3;
#pragma unroll
    for (int i = 0; i < 2; i++) {
#pragma unroll
        for (int j = 0; j < 8; j++) {
            int n = (jg * 8 + j) * 4 + tc;
            int o0 = 2 * n;
            float etf = etf_s[n];
            float wsk = ws_s[o0], wsv = ws_s[o0 + 1];
            float lbk = lb_s[o0], lbv = lb_s[o0 + 1];
#pragma unroll
            for (int h = 0; h < 2; h++) {
                int r = R0 + i * 16 + tr + h * 8;
                float mu = mu_s[r], inv = inv_s[r];
                float k = inv * (acc[i][j][2 * h] - mu * wsk) + lbk;
                float v = inv * (acc[i][j][2 * h + 1] - mu * wsv) + lbv;
                wkv_s[r * 68 + n] = expf(-etf * k) * v;
            }
        }
    }
    __syncthreads();

    // ---- coalesced g_wkv store ----
    {
        int rr = tid >> 1;
        int seg = tid & 1;
        float* dst = &g_wkv[((size_t)(b * SS) + t0 + rr) * NN + seg * 32];
        const float* src = &wkv_s[rr * 68 + seg * 32];
#pragma unroll
        for (int k4 = 0; k4 < 8; k4++)
            reinterpret_cast<float4*>(dst)[k4] = *reinterpret_cast<const float4*>(src + 4 * k4);
    }
    // ---- chunk sums (4 sub-chunks of 32 rows) ----
    {
        int sub = tid >> 6;
        int n = tid & 63;
        float w = g_w[n];
        float a = 0.f;
#pragma unroll
        for (int r2 = 0; r2 < 32; r2++) a = a * w + wkv_s[(sub * 32 + r2) * 68 + n];
        g_chunk[((size_t)b * NCH + tp * 4 + sub) * NN + n] = a;
    }
}

// ---------------- carry prefix over chunks ----------------
__global__ void scan_carry(const float* __restrict__ td, float* __restrict__ lastout,
                           int write_last) {
    int tid = threadIdx.x;
    int n = tid & (NN - 1);
    int b = tid >> 6;
    float wL = expf((float)CHL * td[n]);
    float carry = 0.f;
    for (int c0 = 0; c0 < NCH; c0 += 8) {
        float v[8];
#pragma unroll
        for (int i = 0; i < 8; i++) v[i] = g_chunk[((size_t)b * NCH + c0 + i) * NN + n];
#pragma unroll
        for (int i = 0; i < 8; i++) {
            g_carry[((size_t)b * NCH + c0 + i) * NN + n] = carry;
            carry = carry * wL + v[i];
        }
    }
    if (write_last) lastout[b * NN + n] = carry;
}

// ---------------- kernel C: fused scan + output projection ----------------
#define SPITCH 36
__global__ void __launch_bounds__(1024, 1)
kernelC(float* __restrict__ out) {
    __shared__ float wk[TILE_C * NN];
    __shared__ float sT[NN * SPITCH];

    int b = blockIdx.x >> 7;
    int c = blockIdx.x & 127;
    int t0 = c * TILE_C;
    int tid = threadIdx.x;
    int wg = tid >> 9;
    int dtid = tid & 511;

    if (tid < 512)
        reinterpret_cast<float4*>(wk)[tid] =
            reinterpret_cast<const float4*>(&g_wkv[((size_t)(b * SS) + t0) * NN])[tid];
    __syncthreads();

    if (tid < NN) {
        int n = tid;
        float w = g_w[n];
        float st = g_carry[((size_t)b * NCH + c) * NN + n];
#pragma unroll
        for (int r = 0; r < TILE_C; r++) {
            st = st * w + wk[r * NN + n];
            sT[n * SPITCH + r] = st;
        }
    }
    __syncthreads();

    float2 acc[8][2];
#pragma unroll
    for (int p = 0; p < 8; p++) { acc[p][0] = make_float2(0.f, 0.f); acc[p][1] = make_float2(0.f, 0.f); }

    const float* sBase = &sT[wg * 16];
#pragma unroll 2
    for (int n4 = 0; n4 < 16; n4++) {
        float4 wA = __ldg(&g_owQ[n4 * 1024 + dtid]);
        float4 wB = __ldg(&g_owQ[n4 * 1024 + 512 + dtid]);
#pragma unroll
        for (int j = 0; j < 4; j++) {
            int n = 4 * n4 + j;
            float wa = (j == 0) ? wA.x : (j == 1) ? wA.y : (j == 2) ? wA.z : wA.w;
            float wb2v = (j == 0) ? wB.x : (j == 1) ? wB.y : (j == 2) ? wB.z : wB.w;
            float2 wa2 = make_float2(wa, wa);
            float2 wb2 = make_float2(wb2v, wb2v);
            const float* sb = sBase + n * SPITCH;
#pragma unroll
            for (int qq = 0; qq < 4; qq++) {
                float4 s4 = *reinterpret_cast<const float4*>(sb + 4 * qq);
                float2 slo = make_float2(s4.x, s4.y);
                float2 shi = make_float2(s4.z, s4.w);
                acc[2 * qq][0]     = ffma2(slo, wa2, acc[2 * qq][0]);
                acc[2 * qq][1]     = ffma2(slo, wb2, acc[2 * qq][1]);
                acc[2 * qq + 1][0] = ffma2(shi, wa2, acc[2 * qq + 1][0]);
                acc[2 * qq + 1][1] = ffma2(shi, wb2, acc[2 * qq + 1][1]);
            }
        }
    }

    float* ob = out + ((size_t)(b * SS) + t0 + wg * 16) * DD;
#pragma unroll
    for (int p = 0; p < 8; p++) {
        ob[(size_t)(2 * p) * DD + dtid]           = acc[p][0].x;
        ob[(size_t)(2 * p + 1) * DD + dtid]       = acc[p][0].y;
        ob[(size_t)(2 * p) * DD + 512 + dtid]     = acc[p][1].x;
        ob[(size_t)(2 * p + 1) * DD + 512 + dtid] = acc[p][1].y;
    }
}

// ---------------- launch ----------------
extern "C" void kernel_launch(void* const* d_in, const int* in_sizes, int n_in,
                              void* d_out, int out_size) {
    const float* x   = (const float*)d_in[0];
    const float* td  = (const float*)d_in[1];
    const float* tf  = (const float*)d_in[2];
    const float* kw  = (const float*)d_in[3];
    const float* vw  = (const float*)d_in[4];
    const float* ow  = (const float*)d_in[5];
    const float* tsg = (const float*)d_in[6];
    const float* lnw = (const float*)d_in[7];
    const float* lnb = (const float*)d_in[8];
    float* out = (float*)d_out;

    cudaFuncSetAttribute(kernelA, cudaFuncAttributeMaxDynamicSharedMemorySize, SMEM_A_BYTES);

    prep_a<<<(DD * 128) / 256, 256>>>(kw, vw, lnw, tsg, td, tf);
    prep_bfrag<<<128, 256>>>(ow);
    prep_b<<<128, 256>>>(kw, vw, lnb);
    kernelA<<<BB * 32, 256, SMEM_A_BYTES>>>(x);
    int write_last = (out_size >= BB * SS * DD + BB * NN) ? 1 : 0;
    scan_carry<<<1, 512>>>(td, out + (size_t)BB * SS * DD, write_last);
    kernelC<<<BB * (SS / TILE_C), 1024>>>(out);
}

// round 15
// speedup vs baseline: 1.0300x; 1.0300x over previous
#include <cuda_runtime.h>
#include <cuda_fp16.h>
#include <cstdint>
#include <math.h>

#define BB 8
#define SS 4096
#define DD 1024
#define NN 64
#define SHIFT 2048
#define NCH 128
#define CHL 32
#define TILE_C 32

// ---------------- scratch (device globals) ----------------
__device__ float g_wT[DD * 128];            // [d][o]: o=2n -> lnw*kw, o=2n+1 -> lnw*vw
__device__ float g_wsum[128];
__device__ float g_lbsum[128];
__device__ float g_gate[DD];
__device__ float g_w[NN];                   // exp(time_decay)
__device__ float g_exptf[NN];               // exp(time_first)
__device__ float4 g_owQ[16 * DD];           // [n4][d] = ow[d][4n4..4n4+3]
__device__ uint2 g_bfragH[16 * 2048];       // frag-major fp16 weights: [ch][k16][n8][lane] = (b0,b1)
__device__ float g_wkv[BB * SS * NN];
__device__ float g_chunk[BB * NCH * NN];
__device__ float g_carry[BB * NCH * NN];

// ---------------- packed fp32x2 FMA ----------------
__device__ __forceinline__ float2 ffma2(float2 a, float2 b, float2 c) {
    float2 d;
    asm("fma.rn.f32x2 %0, %1, %2, %3;"
        : "=l"(*reinterpret_cast<unsigned long long*>(&d))
        : "l"(*reinterpret_cast<unsigned long long*>(&a)),
          "l"(*reinterpret_cast<unsigned long long*>(&b)),
          "l"(*reinterpret_cast<unsigned long long*>(&c)));
    return d;
}

// ---------------- HMMA helpers (sm_80+ baseline) ----------------
__device__ __forceinline__ void mma_f16(float* c, const unsigned* a, unsigned b0, unsigned b1) {
    asm volatile("mma.sync.aligned.m16n8k16.row.col.f32.f16.f16.f32 "
                 "{%0,%1,%2,%3}, {%4,%5,%6,%7}, {%8,%9}, {%0,%1,%2,%3};"
                 : "+f"(c[0]), "+f"(c[1]), "+f"(c[2]), "+f"(c[3])
                 : "r"(a[0]), "r"(a[1]), "r"(a[2]), "r"(a[3]), "r"(b0), "r"(b1));
}
__device__ __forceinline__ void ldm4(unsigned* r, unsigned addr) {
    asm volatile("ldmatrix.sync.aligned.m8n8.x4.shared.b16 {%0,%1,%2,%3}, [%4];"
                 : "=r"(r[0]), "=r"(r[1]), "=r"(r[2]), "=r"(r[3]) : "r"(addr));
}
__device__ __forceinline__ unsigned packh(float a, float b) {
    __half2 t = __floats2half2_rn(a, b);
    return *reinterpret_cast<unsigned*>(&t);
}
__device__ __forceinline__ float h2f(float a) {
    return __half2float(__float2half_rn(a));
}
#define PAIR_BAR(id) asm volatile("bar.sync %0, 64;" :: "r"(id) : "memory")

// ---------------- prep kernels ----------------
__global__ void prep_a(const float* __restrict__ kw, const float* __restrict__ vw,
                       const float* __restrict__ lnw, const float* __restrict__ tsg,
                       const float* __restrict__ td, const float* __restrict__ tf) {
    int idx = blockIdx.x * 256 + threadIdx.x;
    int d = idx >> 7;
    int o = idx & 127;
    int n = o >> 1;
    const float* src = (o & 1) ? vw : kw;
    g_wT[idx] = lnw[d] * src[n * DD + d];
    if (o == 0) g_gate[d] = 1.f / (1.f + expf(-tsg[d]));
    if (idx < NN) g_w[idx] = expf(td[idx]);
    else if (idx < 2 * NN) g_exptf[idx - NN] = expf(tf[idx - NN]);
}

// fp16 fragment-major weight pack + ow transpose
__global__ void prep_bfrag(const float* __restrict__ ow) {
    int idx = blockIdx.x * 256 + threadIdx.x;   // 0..32767
    int lane = idx & 31;
    int n8 = (idx >> 5) & 15;
    int s = (idx >> 9) & 3;
    int ch = idx >> 11;
    int o = n8 * 8 + (lane >> 2);
    int kb = ch * 64 + s * 16 + (lane & 3) * 2;
    float w0 = g_wT[(size_t)kb * 128 + o];
    float w1 = g_wT[(size_t)(kb + 1) * 128 + o];
    float w8 = g_wT[(size_t)(kb + 8) * 128 + o];
    float w9 = g_wT[(size_t)(kb + 9) * 128 + o];
    g_bfragH[idx] = make_uint2(packh(w0, w1), packh(w8, w9));
    if (idx < 16384) {
        int d = idx & (DD - 1);
        int n4 = idx >> 10;
        g_owQ[idx] = *reinterpret_cast<const float4*>(&ow[d * NN + 4 * n4]);
    }
}

__global__ void prep_b(const float* __restrict__ kw, const float* __restrict__ vw,
                       const float* __restrict__ lnb) {
    __shared__ float red[2][8];
    int o = blockIdx.x;
    int n = o >> 1;
    const float* src = (o & 1) ? vw : kw;
    int tid = threadIdx.x;
    float ws = 0.f, lb = 0.f;
    for (int d = tid; d < DD; d += 256) {
        ws += g_wT[d * 128 + o];
        lb += lnb[d] * src[n * DD + d];
    }
#pragma unroll
    for (int off = 16; off; off >>= 1) {
        ws += __shfl_xor_sync(0xffffffffu, ws, off);
        lb += __shfl_xor_sync(0xffffffffu, lb, off);
    }
    if ((tid & 31) == 0) { red[0][tid >> 5] = ws; red[1][tid >> 5] = lb; }
    __syncthreads();
    if (tid == 0) {
        float a = 0.f, c = 0.f;
#pragma unroll
        for (int i = 0; i < 8; i++) { a += red[0][i]; c += red[1][i]; }
        g_wsum[o] = a;
        g_lbsum[o] = c;
    }
}

// ---------------- kernel A: HMMA fp16-split KV projection (pair-decoupled) ----------------
// grid 256 (8 b x 32 tiles of 128 rows), 256 threads, occ 2.
// Warp pair p = tid>>6 owns rows 32p..32p+31 (staging AND compute);
// warp = 2p+jg, jg = col half. Pairs synchronize only among themselves
// (named barrier p+1, 64 threads) -> 8 independent pipelines per SM.
// B fragments from L2 via batched __ldg.
// smem: Ah 0..18432 | Al 18432..36864 | consts to 39168
#define SM_AH 0
#define SM_AL 18432
#define SM_MU 36864
#define SM_INV 37376
#define SM_WS 37888
#define SM_LB 38400
#define SM_ETF 38912
#define SMEM_A_BYTES 39168

__global__ void __launch_bounds__(256, 2)
kernelA(const float* __restrict__ x) {
    extern __shared__ char smc[];
    unsigned sbase = (unsigned)__cvta_generic_to_shared(smc);

    int b = blockIdx.x >> 5;
    int tp = blockIdx.x & 31;
    int t0 = tp * 128;
    int tid = threadIdx.x;
    int lane = tid & 31;
    int warp = tid >> 5;
    int p = tid >> 6;                   // pair id 0..3
    int jg = warp & 1;                  // col half
    int R0 = p * 32;
    int q = tid & 63;
    int row = R0 + (q >> 1);            // staging row (within own pair)
    int khalf = (q & 1) * 32;           // float offset within 64-d chunk

    float* mu_s  = reinterpret_cast<float*>(smc + SM_MU);
    float* inv_s = reinterpret_cast<float*>(smc + SM_INV);
    float* ws_s  = reinterpret_cast<float*>(smc + SM_WS);
    float* lb_s  = reinterpret_cast<float*>(smc + SM_LB);
    float* etf_s = reinterpret_cast<float*>(smc + SM_ETF);
    if (tid < 128) {
        ws_s[tid] = g_wsum[tid];
        lb_s[tid] = g_lbsum[tid];
        if (tid < 64) etf_s[tid] = g_exptf[tid];
    }

    const float4* xt4 = reinterpret_cast<const float4*>(x + ((size_t)(b * SS) + t0 + row) * DD);
    const float4* xc4 = reinterpret_cast<const float4*>(x + ((size_t)(b * SS) + ((t0 + row) ^ SHIFT)) * DD);
    const float4* g4 = reinterpret_cast<const float4*>(g_gate);

    float ssum = 0.f, ssq = 0.f;
    float acc[2][8][4];
#pragma unroll
    for (int i = 0; i < 2; i++)
#pragma unroll
        for (int j = 0; j < 8; j++)
#pragma unroll
            for (int c = 0; c < 4; c++) acc[i][j][c] = 0.f;

    char* ah = smc + SM_AH;
    char* al = smc + SM_AL;

#pragma unroll 1
    for (int ch = 0; ch < 16; ch++) {
        // ---- stage own pair's A rows: blend + stats + fp16 hi/lo split ----
#pragma unroll
        for (int i = 0; i < 8; i++) {
            int f4i = ch * 16 + (q & 1) * 8 + i;
            float4 xv = xt4[f4i];
            float4 xc = xc4[f4i];
            float4 g = __ldg(&g4[f4i]);
            float s0 = xv.x + g.x * (xc.x - xv.x);
            float s1 = xv.y + g.y * (xc.y - xv.y);
            float s2 = xv.z + g.z * (xc.z - xv.z);
            float s3 = xv.w + g.w * (xc.w - xv.w);
            ssum += s0 + s1 + s2 + s3;
            ssq  += s0 * s0 + s1 * s1 + s2 * s2 + s3 * s3;
            float h0 = h2f(s0), h1 = h2f(s1), h2 = h2f(s2), h3 = h2f(s3);
            int klocal = khalf + i * 4;
            *reinterpret_cast<uint2*>(ah + row * 144 + klocal * 2) =
                make_uint2(packh(h0, h1), packh(h2, h3));
            *reinterpret_cast<uint2*>(al + row * 144 + klocal * 2) =
                make_uint2(packh(s0 - h0, s1 - h1), packh(s2 - h2, s3 - h3));
        }
        PAIR_BAR(p + 1);   // pair staging visible

        // ---- compute: 4 k16 x (2 m16 x 8 n8) x 2 split-MMAs; B from L2, batched ----
        const uint2* bgl = &g_bfragH[ch * 2048 + (jg * 8) * 32 + lane];
#pragma unroll
        for (int k16 = 0; k16 < 4; k16++) {
            uint2 Bv[8];
#pragma unroll
            for (int j = 0; j < 8; j++) Bv[j] = __ldg(&bgl[(k16 * 16 + j) * 32]);
            unsigned kofs = (unsigned)((k16 * 16 + ((lane & 16) ? 8 : 0)) * 2);
            unsigned a_h[2][4], a_l[2][4];
#pragma unroll
            for (int i = 0; i < 2; i++) {
                unsigned aoff = (unsigned)((R0 + i * 16 + (lane & 15)) * 144) + kofs;
                ldm4(a_h[i], sbase + SM_AH + aoff);
                ldm4(a_l[i], sbase + SM_AL + aoff);
            }
#pragma unroll
            for (int j = 0; j < 8; j++) {
                mma_f16(acc[0][j], a_h[0], Bv[j].x, Bv[j].y);
                mma_f16(acc[0][j], a_l[0], Bv[j].x, Bv[j].y);
                mma_f16(acc[1][j], a_h[1], Bv[j].x, Bv[j].y);
                mma_f16(acc[1][j], a_l[1], Bv[j].x, Bv[j].y);
            }
        }
        PAIR_BAR(p + 1);   // compute done before next overwrite
    }

    // ---- LN stats finalize (adjacent lanes share a row) ----
    ssum += __shfl_xor_sync(0xffffffffu, ssum, 1);
    ssq  += __shfl_xor_sync(0xffffffffu, ssq, 1);
    if ((q & 1) == 0) {
        float mu = ssum * (1.f / DD);
        float var = ssq * (1.f / DD) - mu * mu;
        mu_s[row] = mu;
        inv_s[row] = rsqrtf(var + 1e-5f);
    }
    __syncthreads();

    // ---- epilogue: LN fold + wkv -> smem (overlay A region, pitch 68) ----
    float* wkv_s = reinterpret_cast<float*>(smc);
    int tr = lane >> 2, tc = lane & 3;
#pragma unroll
    for (int i = 0; i < 2; i++) {
#pragma unroll
        for (int j = 0; j < 8; j++) {
            int n = (jg * 8 + j) * 4 + tc;
            int o0 = 2 * n;
            float etf = etf_s[n];
            float wsk = ws_s[o0], wsv = ws_s[o0 + 1];
            float lbk = lb_s[o0], lbv = lb_s[o0 + 1];
#pragma unroll
            for (int h = 0; h < 2; h++) {
                int r = R0 + i * 16 + tr + h * 8;
                float mu = mu_s[r], inv = inv_s[r];
                float k = inv * (acc[i][j][2 * h] - mu * wsk) + lbk;
                float v = inv * (acc[i][j][2 * h + 1] - mu * wsv) + lbv;
                wkv_s[r * 68 + n] = expf(-etf * k) * v;
            }
        }
    }
    __syncthreads();

    // ---- coalesced g_wkv store ----
    {
        int rr = tid >> 1;
        int seg = tid & 1;
        float* dst = &g_wkv[((size_t)(b * SS) + t0 + rr) * NN + seg * 32];
        const float* src = &wkv_s[rr * 68 + seg * 32];
#pragma unroll
        for (int k4 = 0; k4 < 8; k4++)
            reinterpret_cast<float4*>(dst)[k4] = *reinterpret_cast<const float4*>(src + 4 * k4);
    }
    // ---- chunk sums (4 sub-chunks of 32 rows) ----
    {
        int sub = tid >> 6;
        int n = tid & 63;
        float w = g_w[n];
        float a = 0.f;
#pragma unroll
        for (int r2 = 0; r2 < 32; r2++) a = a * w + wkv_s[(sub * 32 + r2) * 68 + n];
        g_chunk[((size_t)b * NCH + tp * 4 + sub) * NN + n] = a;
    }
}

// ---------------- carry prefix over chunks ----------------
__global__ void scan_carry(const float* __restrict__ td, float* __restrict__ lastout,
                           int write_last) {
    int tid = threadIdx.x;
    int n = tid & (NN - 1);
    int b = tid >> 6;
    float wL = expf((float)CHL * td[n]);
    float carry = 0.f;
    for (int c0 = 0; c0 < NCH; c0 += 8) {
        float v[8];
#pragma unroll
        for (int i = 0; i < 8; i++) v[i] = g_chunk[((size_t)b * NCH + c0 + i) * NN + n];
#pragma unroll
        for (int i = 0; i < 8; i++) {
            g_carry[((size_t)b * NCH + c0 + i) * NN + n] = carry;
            carry = carry * wL + v[i];
        }
    }
    if (write_last) lastout[b * NN + n] = carry;
}

// ---------------- kernel C: fused scan + output projection ----------------
#define SPITCH 36
__global__ void __launch_bounds__(1024, 1)
kernelC(float* __restrict__ out) {
    __shared__ float wk[TILE_C * NN];
    __shared__ float sT[NN * SPITCH];

    int b = blockIdx.x >> 7;
    int c = blockIdx.x & 127;
    int t0 = c * TILE_C;
    int tid = threadIdx.x;
    int wg = tid >> 9;
    int dtid = tid & 511;

    if (tid < 512)
        reinterpret_cast<float4*>(wk)[tid] =
            reinterpret_cast<const float4*>(&g_wkv[((size_t)(b * SS) + t0) * NN])[tid];
    __syncthreads();

    if (tid < NN) {
        int n = tid;
        float w = g_w[n];
        float st = g_carry[((size_t)b * NCH + c) * NN + n];
#pragma unroll
        for (int r = 0; r < TILE_C; r++) {
            st = st * w + wk[r * NN + n];
            sT[n * SPITCH + r] = st;
        }
    }
    __syncthreads();

    float2 acc[8][2];
#pragma unroll
    for (int pp = 0; pp < 8; pp++) { acc[pp][0] = make_float2(0.f, 0.f); acc[pp][1] = make_float2(0.f, 0.f); }

    const float* sBase = &sT[wg * 16];
#pragma unroll 2
    for (int n4 = 0; n4 < 16; n4++) {
        float4 wA = __ldg(&g_owQ[n4 * 1024 + dtid]);
        float4 wB = __ldg(&g_owQ[n4 * 1024 + 512 + dtid]);
#pragma unroll
        for (int j = 0; j < 4; j++) {
            int n = 4 * n4 + j;
            float wa = (j == 0) ? wA.x : (j == 1) ? wA.y : (j == 2) ? wA.z : wA.w;
            float wb2v = (j == 0) ? wB.x : (j == 1) ? wB.y : (j == 2) ? wB.z : wB.w;
            float2 wa2 = make_float2(wa, wa);
            float2 wb2 = make_float2(wb2v, wb2v);
            const float* sb = sBase + n * SPITCH;
#pragma unroll
            for (int qq = 0; qq < 4; qq++) {
                float4 s4 = *reinterpret_cast<const float4*>(sb + 4 * qq);
                float2 slo = make_float2(s4.x, s4.y);
                float2 shi = make_float2(s4.z, s4.w);
                acc[2 * qq][0]     = ffma2(slo, wa2, acc[2 * qq][0]);
                acc[2 * qq][1]     = ffma2(slo, wb2, acc[2 * qq][1]);
                acc[2 * qq + 1][0] = ffma2(shi, wa2, acc[2 * qq + 1][0]);
                acc[2 * qq + 1][1] = ffma2(shi, wb2, acc[2 * qq + 1][1]);
            }
        }
    }

    float* ob = out + ((size_t)(b * SS) + t0 + wg * 16) * DD;
#pragma unroll
    for (int pp = 0; pp < 8; pp++) {
        ob[(size_t)(2 * pp) * DD + dtid]           = acc[pp][0].x;
        ob[(size_t)(2 * pp + 1) * DD + dtid]       = acc[pp][0].y;
        ob[(size_t)(2 * pp) * DD + 512 + dtid]     = acc[pp][1].x;
        ob[(size_t)(2 * pp + 1) * DD + 512 + dtid] = acc[pp][1].y;
    }
}

// ---------------- launch ----------------
extern "C" void kernel_launch(void* const* d_in, const int* in_sizes, int n_in,
                              void* d_out, int out_size) {
    const float* x   = (const float*)d_in[0];
    const float* td  = (const float*)d_in[1];
    const float* tf  = (const float*)d_in[2];
    const float* kw  = (const float*)d_in[3];
    const float* vw  = (const float*)d_in[4];
    const float* ow  = (const float*)d_in[5];
    const float* tsg = (const float*)d_in[6];
    const float* lnw = (const float*)d_in[7];
    const float* lnb = (const float*)d_in[8];
    float* out = (float*)d_out;

    cudaFuncSetAttribute(kernelA, cudaFuncAttributeMaxDynamicSharedMemorySize, SMEM_A_BYTES);

    prep_a<<<(DD * 128) / 256, 256>>>(kw, vw, lnw, tsg, td, tf);
    prep_bfrag<<<128, 256>>>(ow);
    prep_b<<<128, 256>>>(kw, vw, lnb);
    kernelA<<<BB * 32, 256, SMEM_A_BYTES>>>(x);
    int write_last = (out_size >= BB * SS * DD + BB * NN) ? 1 : 0;
    scan_carry<<<1, 512>>>(td, out + (size_t)BB * SS * DD, write_last);
    kernelC<<<BB * (SS / TILE_C), 1024>>>(out);
}

// round 16
// speedup vs baseline: 1.1303x; 1.0974x over previous
#include <cuda_runtime.h>
#include <cuda_fp16.h>
#include <cstdint>
#include <math.h>

#define BB 8
#define SS 4096
#define DD 1024
#define NN 64
#define SHIFT 2048
#define NCH 128
#define CHL 32
#define TILE_C 32

// ---------------- scratch (device globals) ----------------
__device__ float g_wT[DD * 128];            // [d][o]: o=2n -> lnw*kw, o=2n+1 -> lnw*vw
__device__ float g_wsum[128];
__device__ float g_lbsum[128];
__device__ float g_gate[DD];
__device__ float g_w[NN];                   // exp(time_decay)
__device__ float g_exptf[NN];               // exp(time_first)
__device__ uint2 g_bfragH[16 * 2048];       // frag-major fp16 KV weights
__device__ uint2 g_owfH[4 * 128 * 32];      // frag-major fp16 ow hi: [k16][n8(d)][lane]
__device__ uint2 g_owfL[4 * 128 * 32];      // lo residuals
__device__ float g_wkv[BB * SS * NN];
__device__ float g_chunk[BB * NCH * NN];
__device__ float g_carry[BB * NCH * NN];

// ---------------- HMMA helpers (sm_80+ baseline) ----------------
__device__ __forceinline__ void mma_f16(float* c, const unsigned* a, unsigned b0, unsigned b1) {
    asm volatile("mma.sync.aligned.m16n8k16.row.col.f32.f16.f16.f32 "
                 "{%0,%1,%2,%3}, {%4,%5,%6,%7}, {%8,%9}, {%0,%1,%2,%3};"
                 : "+f"(c[0]), "+f"(c[1]), "+f"(c[2]), "+f"(c[3])
                 : "r"(a[0]), "r"(a[1]), "r"(a[2]), "r"(a[3]), "r"(b0), "r"(b1));
}
__device__ __forceinline__ void ldm4(unsigned* r, unsigned addr) {
    asm volatile("ldmatrix.sync.aligned.m8n8.x4.shared.b16 {%0,%1,%2,%3}, [%4];"
                 : "=r"(r[0]), "=r"(r[1]), "=r"(r[2]), "=r"(r[3]) : "r"(addr));
}
__device__ __forceinline__ unsigned packh(float a, float b) {
    __half2 t = __floats2half2_rn(a, b);
    return *reinterpret_cast<unsigned*>(&t);
}
__device__ __forceinline__ float h2f(float a) {
    return __half2float(__float2half_rn(a));
}
#define PAIR_BAR(id) asm volatile("bar.sync %0, 64;" :: "r"(id) : "memory")

// ---------------- prep kernels ----------------
__global__ void prep_a(const float* __restrict__ kw, const float* __restrict__ vw,
                       const float* __restrict__ lnw, const float* __restrict__ tsg,
                       const float* __restrict__ td, const float* __restrict__ tf) {
    int idx = blockIdx.x * 256 + threadIdx.x;
    int d = idx >> 7;
    int o = idx & 127;
    int n = o >> 1;
    const float* src = (o & 1) ? vw : kw;
    g_wT[idx] = lnw[d] * src[n * DD + d];
    if (o == 0) g_gate[d] = 1.f / (1.f + expf(-tsg[d]));
    if (idx < NN) g_w[idx] = expf(td[idx]);
    else if (idx < 2 * NN) g_exptf[idx - NN] = expf(tf[idx - NN]);
}

// fp16 fragment packs: KV weights (single fp16) + ow (hi/lo split)
__global__ void prep_frag(const float* __restrict__ ow) {
    int idx = blockIdx.x * 256 + threadIdx.x;   // 0..32767
    int lane = idx & 31;
    {
        int n8 = (idx >> 5) & 15;
        int s = (idx >> 9) & 3;
        int ch = idx >> 11;
        int o = n8 * 8 + (lane >> 2);
        int kb = ch * 64 + s * 16 + (lane & 3) * 2;
        float w0 = g_wT[(size_t)kb * 128 + o];
        float w1 = g_wT[(size_t)(kb + 1) * 128 + o];
        float w8 = g_wT[(size_t)(kb + 8) * 128 + o];
        float w9 = g_wT[(size_t)(kb + 9) * 128 + o];
        g_bfragH[idx] = make_uint2(packh(w0, w1), packh(w8, w9));
    }
    if (idx < 16384) {
        int j = (idx >> 5) & 127;               // d-tile
        int s = idx >> 12;                      // k16
        int d = j * 8 + (lane >> 2);
        int kb = s * 16 + (lane & 3) * 2;
        float w0 = ow[d * NN + kb];
        float w1 = ow[d * NN + kb + 1];
        float w8 = ow[d * NN + kb + 8];
        float w9 = ow[d * NN + kb + 9];
        float h0 = h2f(w0), h1 = h2f(w1), h8 = h2f(w8), h9 = h2f(w9);
        g_owfH[idx] = make_uint2(packh(h0, h1), packh(h8, h9));
        g_owfL[idx] = make_uint2(packh(w0 - h0, w1 - h1), packh(w8 - h8, w9 - h9));
    }
}

__global__ void prep_b(const float* __restrict__ kw, const float* __restrict__ vw,
                       const float* __restrict__ lnb) {
    __shared__ float red[2][8];
    int o = blockIdx.x;
    int n = o >> 1;
    const float* src = (o & 1) ? vw : kw;
    int tid = threadIdx.x;
    float ws = 0.f, lb = 0.f;
    for (int d = tid; d < DD; d += 256) {
        ws += g_wT[d * 128 + o];
        lb += lnb[d] * src[n * DD + d];
    }
#pragma unroll
    for (int off = 16; off; off >>= 1) {
        ws += __shfl_xor_sync(0xffffffffu, ws, off);
        lb += __shfl_xor_sync(0xffffffffu, lb, off);
    }
    if ((tid & 31) == 0) { red[0][tid >> 5] = ws; red[1][tid >> 5] = lb; }
    __syncthreads();
    if (tid == 0) {
        float a = 0.f, c = 0.f;
#pragma unroll
        for (int i = 0; i < 8; i++) { a += red[0][i]; c += red[1][i]; }
        g_wsum[o] = a;
        g_lbsum[o] = c;
    }
}

// ---------------- kernel A: HMMA fp16-split KV projection (pair-decoupled, R15) ----------------
#define SM_AH 0
#define SM_AL 18432
#define SM_MU 36864
#define SM_INV 37376
#define SM_WS 37888
#define SM_LB 38400
#define SM_ETF 38912
#define SMEM_A_BYTES 39168

__global__ void __launch_bounds__(256, 2)
kernelA(const float* __restrict__ x) {
    extern __shared__ char smc[];
    unsigned sbase = (unsigned)__cvta_generic_to_shared(smc);

    int b = blockIdx.x >> 5;
    int tp = blockIdx.x & 31;
    int t0 = tp * 128;
    int tid = threadIdx.x;
    int lane = tid & 31;
    int warp = tid >> 5;
    int p = tid >> 6;                   // pair id 0..3
    int jg = warp & 1;                  // col half
    int R0 = p * 32;
    int q = tid & 63;
    int row = R0 + (q >> 1);
    int khalf = (q & 1) * 32;

    float* mu_s  = reinterpret_cast<float*>(smc + SM_MU);
    float* inv_s = reinterpret_cast<float*>(smc + SM_INV);
    float* ws_s  = reinterpret_cast<float*>(smc + SM_WS);
    float* lb_s  = reinterpret_cast<float*>(smc + SM_LB);
    float* etf_s = reinterpret_cast<float*>(smc + SM_ETF);
    if (tid < 128) {
        ws_s[tid] = g_wsum[tid];
        lb_s[tid] = g_lbsum[tid];
        if (tid < 64) etf_s[tid] = g_exptf[tid];
    }

    const float4* xt4 = reinterpret_cast<const float4*>(x + ((size_t)(b * SS) + t0 + row) * DD);
    const float4* xc4 = reinterpret_cast<const float4*>(x + ((size_t)(b * SS) + ((t0 + row) ^ SHIFT)) * DD);
    const float4* g4 = reinterpret_cast<const float4*>(g_gate);

    float ssum = 0.f, ssq = 0.f;
    float acc[2][8][4];
#pragma unroll
    for (int i = 0; i < 2; i++)
#pragma unroll
        for (int j = 0; j < 8; j++)
#pragma unroll
            for (int c = 0; c < 4; c++) acc[i][j][c] = 0.f;

    char* ah = smc + SM_AH;
    char* al = smc + SM_AL;

#pragma unroll 1
    for (int ch = 0; ch < 16; ch++) {
#pragma unroll
        for (int i = 0; i < 8; i++) {
            int f4i = ch * 16 + (q & 1) * 8 + i;
            float4 xv = xt4[f4i];
            float4 xc = xc4[f4i];
            float4 g = __ldg(&g4[f4i]);
            float s0 = xv.x + g.x * (xc.x - xv.x);
            float s1 = xv.y + g.y * (xc.y - xv.y);
            float s2 = xv.z + g.z * (xc.z - xv.z);
            float s3 = xv.w + g.w * (xc.w - xv.w);
            ssum += s0 + s1 + s2 + s3;
            ssq  += s0 * s0 + s1 * s1 + s2 * s2 + s3 * s3;
            float h0 = h2f(s0), h1 = h2f(s1), h2 = h2f(s2), h3 = h2f(s3);
            int klocal = khalf + i * 4;
            *reinterpret_cast<uint2*>(ah + row * 144 + klocal * 2) =
                make_uint2(packh(h0, h1), packh(h2, h3));
            *reinterpret_cast<uint2*>(al + row * 144 + klocal * 2) =
                make_uint2(packh(s0 - h0, s1 - h1), packh(s2 - h2, s3 - h3));
        }
        PAIR_BAR(p + 1);

        const uint2* bgl = &g_bfragH[ch * 2048 + (jg * 8) * 32 + lane];
#pragma unroll
        for (int k16 = 0; k16 < 4; k16++) {
            uint2 Bv[8];
#pragma unroll
            for (int j = 0; j < 8; j++) Bv[j] = __ldg(&bgl[(k16 * 16 + j) * 32]);
            unsigned kofs = (unsigned)((k16 * 16 + ((lane & 16) ? 8 : 0)) * 2);
            unsigned a_h[2][4], a_l[2][4];
#pragma unroll
            for (int i = 0; i < 2; i++) {
                unsigned aoff = (unsigned)((R0 + i * 16 + (lane & 15)) * 144) + kofs;
                ldm4(a_h[i], sbase + SM_AH + aoff);
                ldm4(a_l[i], sbase + SM_AL + aoff);
            }
#pragma unroll
            for (int j = 0; j < 8; j++) {
                mma_f16(acc[0][j], a_h[0], Bv[j].x, Bv[j].y);
                mma_f16(acc[0][j], a_l[0], Bv[j].x, Bv[j].y);
                mma_f16(acc[1][j], a_h[1], Bv[j].x, Bv[j].y);
                mma_f16(acc[1][j], a_l[1], Bv[j].x, Bv[j].y);
            }
        }
        PAIR_BAR(p + 1);
    }

    ssum += __shfl_xor_sync(0xffffffffu, ssum, 1);
    ssq  += __shfl_xor_sync(0xffffffffu, ssq, 1);
    if ((q & 1) == 0) {
        float mu = ssum * (1.f / DD);
        float var = ssq * (1.f / DD) - mu * mu;
        mu_s[row] = mu;
        inv_s[row] = rsqrtf(var + 1e-5f);
    }
    __syncthreads();

    float* wkv_s = reinterpret_cast<float*>(smc);
    int tr = lane >> 2, tc = lane & 3;
#pragma unroll
    for (int i = 0; i < 2; i++) {
#pragma unroll
        for (int j = 0; j < 8; j++) {
            int n = (jg * 8 + j) * 4 + tc;
            int o0 = 2 * n;
            float etf = etf_s[n];
            float wsk = ws_s[o0], wsv = ws_s[o0 + 1];
            float lbk = lb_s[o0], lbv = lb_s[o0 + 1];
#pragma unroll
            for (int h = 0; h < 2; h++) {
                int r = R0 + i * 16 + tr + h * 8;
                float mu = mu_s[r], inv = inv_s[r];
                float k = inv * (acc[i][j][2 * h] - mu * wsk) + lbk;
                float v = inv * (acc[i][j][2 * h + 1] - mu * wsv) + lbv;
                wkv_s[r * 68 + n] = expf(-etf * k) * v;
            }
        }
    }
    __syncthreads();

    {
        int rr = tid >> 1;
        int seg = tid & 1;
        float* dst = &g_wkv[((size_t)(b * SS) + t0 + rr) * NN + seg * 32];
        const float* src = &wkv_s[rr * 68 + seg * 32];
#pragma unroll
        for (int k4 = 0; k4 < 8; k4++)
            reinterpret_cast<float4*>(dst)[k4] = *reinterpret_cast<const float4*>(src + 4 * k4);
    }
    {
        int sub = tid >> 6;
        int n = tid & 63;
        float w = g_w[n];
        float a = 0.f;
#pragma unroll
        for (int r2 = 0; r2 < 32; r2++) a = a * w + wkv_s[(sub * 32 + r2) * 68 + n];
        g_chunk[((size_t)b * NCH + tp * 4 + sub) * NN + n] = a;
    }
}

// ---------------- carry prefix over chunks ----------------
__global__ void scan_carry(const float* __restrict__ td, float* __restrict__ lastout,
                           int write_last) {
    int tid = threadIdx.x;
    int n = tid & (NN - 1);
    int b = tid >> 6;
    float wL = expf((float)CHL * td[n]);
    float carry = 0.f;
    for (int c0 = 0; c0 < NCH; c0 += 8) {
        float v[8];
#pragma unroll
        for (int i = 0; i < 8; i++) v[i] = g_chunk[((size_t)b * NCH + c0 + i) * NN + n];
#pragma unroll
        for (int i = 0; i < 8; i++) {
            g_carry[((size_t)b * NCH + c0 + i) * NN + n] = carry;
            carry = carry * wL + v[i];
        }
    }
    if (write_last) lastout[b * NN + n] = carry;
}

// ---------------- kernel C: fused scan + HMMA output projection ----------------
// grid 1024 (8 b x 128 tiles of 32 rows), 256 threads.
// A = states fp16 hi/lo (exact split), B = ow fp16 hi/lo from L2 (3-term MMA).
// warp = (mi = warp>>2 row-tile, nq = warp&3); each warp: 32 n8 d-tiles.
__global__ void __launch_bounds__(256)
kernelC(float* __restrict__ out) {
    __shared__ float wk[TILE_C * NN];       // 8KB
    __shared__ float sT[NN * 36];           // 9KB
    __shared__ char cA[2][32 * 144];        // fp16 hi/lo state tiles, 4.5KB each

    int b = blockIdx.x >> 7;
    int c = blockIdx.x & 127;
    int t0 = c * TILE_C;
    int tid = threadIdx.x;
    int lane = tid & 31;
    int warp = tid >> 5;

    // load wkv tile (512 float4)
    {
        const float4* src = reinterpret_cast<const float4*>(&g_wkv[((size_t)(b * SS) + t0) * NN]);
        float4* dst = reinterpret_cast<float4*>(wk);
        dst[tid] = src[tid];
        dst[256 + tid] = src[256 + tid];
    }
    __syncthreads();

    // scan: thread n walks 32 rows, stores transposed fp32
    if (tid < NN) {
        int n = tid;
        float w = g_w[n];
        float st = g_carry[((size_t)b * NCH + c) * NN + n];
#pragma unroll
        for (int r = 0; r < TILE_C; r++) {
            st = st * w + wk[r * NN + n];
            sT[n * 36 + r] = st;
        }
    }
    __syncthreads();

    // convert states -> fp16 hi/lo row-major tiles (pitch 144B)
    {
        int r = tid >> 3;                // 0..31
        int seg = tid & 7;               // 8 k's per seg
        float v[8];
#pragma unroll
        for (int j = 0; j < 8; j++) v[j] = sT[(seg * 8 + j) * 36 + r];
        unsigned hp[4], lp[4];
#pragma unroll
        for (int e = 0; e < 4; e++) {
            float a = v[2 * e], bb = v[2 * e + 1];
            float ha = h2f(a), hb = h2f(bb);
            hp[e] = packh(ha, hb);
            lp[e] = packh(a - ha, bb - hb);
        }
        *reinterpret_cast<uint4*>(&cA[0][r * 144 + seg * 16]) = make_uint4(hp[0], hp[1], hp[2], hp[3]);
        *reinterpret_cast<uint4*>(&cA[1][r * 144 + seg * 16]) = make_uint4(lp[0], lp[1], lp[2], lp[3]);
    }
    __syncthreads();

    // load A fragments once per warp
    int mi = warp >> 2;                  // row tile 0..1
    int nq = warp & 3;                   // n8 quarter
    unsigned sbase0 = (unsigned)__cvta_generic_to_shared(&cA[0][0]);
    unsigned sbase1 = (unsigned)__cvta_generic_to_shared(&cA[1][0]);
    unsigned a_h[4][4], a_l[4][4];
#pragma unroll
    for (int k16 = 0; k16 < 4; k16++) {
        unsigned aoff = (unsigned)((mi * 16 + (lane & 15)) * 144 + (k16 * 16 + ((lane & 16) ? 8 : 0)) * 2);
        ldm4(a_h[k16], sbase0 + aoff);
        ldm4(a_l[k16], sbase1 + aoff);
    }

    int tr = lane >> 2, tc = lane & 3;
    float* ob = out + ((size_t)(b * SS) + t0 + mi * 16) * DD;
#pragma unroll 2
    for (int j0 = 0; j0 < 32; j0++) {
        int j = nq * 32 + j0;
        uint2 BH[4], BL[4];
#pragma unroll
        for (int k16 = 0; k16 < 4; k16++) {
            BH[k16] = __ldg(&g_owfH[(k16 * 128 + j) * 32 + lane]);
            BL[k16] = __ldg(&g_owfL[(k16 * 128 + j) * 32 + lane]);
        }
        float accA[4] = {0.f, 0.f, 0.f, 0.f};
        float accB[4] = {0.f, 0.f, 0.f, 0.f};
#pragma unroll
        for (int k16 = 0; k16 < 4; k16++) {
            mma_f16(accA, a_h[k16], BH[k16].x, BH[k16].y);
            mma_f16(accB, a_l[k16], BH[k16].x, BH[k16].y);
            mma_f16(accB, a_h[k16], BL[k16].x, BL[k16].y);
        }
        int d = j * 8 + tc * 2;
        *reinterpret_cast<float2*>(&ob[(size_t)tr * DD + d]) =
            make_float2(accA[0] + accB[0], accA[1] + accB[1]);
        *reinterpret_cast<float2*>(&ob[(size_t)(tr + 8) * DD + d]) =
            make_float2(accA[2] + accB[2], accA[3] + accB[3]);
    }
}

// ---------------- launch ----------------
extern "C" void kernel_launch(void* const* d_in, const int* in_sizes, int n_in,
                              void* d_out, int out_size) {
    const float* x   = (const float*)d_in[0];
    const float* td  = (const float*)d_in[1];
    const float* tf  = (const float*)d_in[2];
    const float* kw  = (const float*)d_in[3];
    const float* vw  = (const float*)d_in[4];
    const float* ow  = (const float*)d_in[5];
    const float* tsg = (const float*)d_in[6];
    const float* lnw = (const float*)d_in[7];
    const float* lnb = (const float*)d_in[8];
    float* out = (float*)d_out;

    cudaFuncSetAttribute(kernelA, cudaFuncAttributeMaxDynamicSharedMemorySize, SMEM_A_BYTES);

    prep_a<<<(DD * 128) / 256, 256>>>(kw, vw, lnw, tsg, td, tf);
    prep_frag<<<128, 256>>>(ow);
    prep_b<<<128, 256>>>(kw, vw, lnb);
    kernelA<<<BB * 32, 256, SMEM_A_BYTES>>>(x);
    int write_last = (out_size >= BB * SS * DD + BB * NN) ? 1 : 0;
    scan_carry<<<1, 512>>>(td, out + (size_t)BB * SS * DD, write_last);
    kernelC<<<BB * (SS / TILE_C), 256>>>(out);
}

// round 17
// speedup vs baseline: 1.2918x; 1.1429x over previous
#include <cuda_runtime.h>
#include <cuda_fp16.h>
#include <cstdint>
#include <math.h>

#define BB 8
#define SS 4096
#define DD 1024
#define NN 64
#define SHIFT 2048
#define NCH 128
#define CHL 32
#define TILE_C 32

// ---------------- scratch (device globals) ----------------
__device__ float g_wT[DD * 128];            // [d][o]: o=2n -> lnw*kw, o=2n+1 -> lnw*vw
__device__ float g_wsum[128];
__device__ float g_lbsum[128];
__device__ float g_gate[DD];
__device__ float g_w[NN];                   // exp(time_decay)
__device__ float g_exptf[NN];               // exp(time_first)
__device__ uint2 g_bfragH[16 * 2048];       // frag-major fp16 KV weights
__device__ uint2 g_owfH[4 * 128 * 32];      // frag-major fp16 ow hi: [k16][n8(d)][lane]
__device__ uint2 g_owfL[4 * 128 * 32];      // lo residuals
__device__ float g_wkv[BB * SS * NN];
__device__ float g_chunk[BB * NCH * NN];
__device__ float g_carry[BB * NCH * NN];

// ---------------- HMMA helpers (sm_80+ baseline) ----------------
__device__ __forceinline__ void mma_f16(float* c, const unsigned* a, unsigned b0, unsigned b1) {
    asm volatile("mma.sync.aligned.m16n8k16.row.col.f32.f16.f16.f32 "
                 "{%0,%1,%2,%3}, {%4,%5,%6,%7}, {%8,%9}, {%0,%1,%2,%3};"
                 : "+f"(c[0]), "+f"(c[1]), "+f"(c[2]), "+f"(c[3])
                 : "r"(a[0]), "r"(a[1]), "r"(a[2]), "r"(a[3]), "r"(b0), "r"(b1));
}
__device__ __forceinline__ void ldm4(unsigned* r, unsigned addr) {
    asm volatile("ldmatrix.sync.aligned.m8n8.x4.shared.b16 {%0,%1,%2,%3}, [%4];"
                 : "=r"(r[0]), "=r"(r[1]), "=r"(r[2]), "=r"(r[3]) : "r"(addr));
}
__device__ __forceinline__ unsigned packh(float a, float b) {
    __half2 t = __floats2half2_rn(a, b);
    return *reinterpret_cast<unsigned*>(&t);
}
__device__ __forceinline__ float h2f(float a) {
    return __half2float(__float2half_rn(a));
}
#define PAIR_BAR(id) asm volatile("bar.sync %0, 64;" :: "r"(id) : "memory")

// ---------------- prep kernels ----------------
__global__ void prep_a(const float* __restrict__ kw, const float* __restrict__ vw,
                       const float* __restrict__ lnw, const float* __restrict__ tsg,
                       const float* __restrict__ td, const float* __restrict__ tf) {
    int idx = blockIdx.x * 256 + threadIdx.x;
    int d = idx >> 7;
    int o = idx & 127;
    int n = o >> 1;
    const float* src = (o & 1) ? vw : kw;
    g_wT[idx] = lnw[d] * src[n * DD + d];
    if (o == 0) g_gate[d] = 1.f / (1.f + expf(-tsg[d]));
    if (idx < NN) g_w[idx] = expf(td[idx]);
    else if (idx < 2 * NN) g_exptf[idx - NN] = expf(tf[idx - NN]);
}

// fp16 fragment packs: KV weights (single fp16) + ow (hi/lo split)
__global__ void prep_frag(const float* __restrict__ ow) {
    int idx = blockIdx.x * 256 + threadIdx.x;   // 0..32767
    int lane = idx & 31;
    {
        int n8 = (idx >> 5) & 15;
        int s = (idx >> 9) & 3;
        int ch = idx >> 11;
        int o = n8 * 8 + (lane >> 2);
        int kb = ch * 64 + s * 16 + (lane & 3) * 2;
        float w0 = g_wT[(size_t)kb * 128 + o];
        float w1 = g_wT[(size_t)(kb + 1) * 128 + o];
        float w8 = g_wT[(size_t)(kb + 8) * 128 + o];
        float w9 = g_wT[(size_t)(kb + 9) * 128 + o];
        g_bfragH[idx] = make_uint2(packh(w0, w1), packh(w8, w9));
    }
    if (idx < 16384) {
        int j = (idx >> 5) & 127;               // d-tile
        int s = idx >> 12;                      // k16
        int d = j * 8 + (lane >> 2);
        int kb = s * 16 + (lane & 3) * 2;
        float w0 = ow[d * NN + kb];
        float w1 = ow[d * NN + kb + 1];
        float w8 = ow[d * NN + kb + 8];
        float w9 = ow[d * NN + kb + 9];
        float h0 = h2f(w0), h1 = h2f(w1), h8 = h2f(w8), h9 = h2f(w9);
        g_owfH[idx] = make_uint2(packh(h0, h1), packh(h8, h9));
        g_owfL[idx] = make_uint2(packh(w0 - h0, w1 - h1), packh(w8 - h8, w9 - h9));
    }
}

__global__ void prep_b(const float* __restrict__ kw, const float* __restrict__ vw,
                       const float* __restrict__ lnb) {
    __shared__ float red[2][8];
    int o = blockIdx.x;
    int n = o >> 1;
    const float* src = (o & 1) ? vw : kw;
    int tid = threadIdx.x;
    float ws = 0.f, lb = 0.f;
    for (int d = tid; d < DD; d += 256) {
        ws += g_wT[d * 128 + o];
        lb += lnb[d] * src[n * DD + d];
    }
#pragma unroll
    for (int off = 16; off; off >>= 1) {
        ws += __shfl_xor_sync(0xffffffffu, ws, off);
        lb += __shfl_xor_sync(0xffffffffu, lb, off);
    }
    if ((tid & 31) == 0) { red[0][tid >> 5] = ws; red[1][tid >> 5] = lb; }
    __syncthreads();
    if (tid == 0) {
        float a = 0.f, c = 0.f;
#pragma unroll
        for (int i = 0; i < 8; i++) { a += red[0][i]; c += red[1][i]; }
        g_wsum[o] = a;
        g_lbsum[o] = c;
    }
}

// ---------------- kernel A: HMMA fp16-split KV projection (coalesced staging) ----------------
// grid 256 (8 b x 32 tiles of 128 rows), 256 threads, occ 2.
// Pair p = tid>>6 owns rows 32p..32p+31. Staging: thread q -> fg=(q&7)*2 float4 cols,
// rq=q>>3 row-in-8; per warp instr: 4 rows x 128B contiguous = 4 wavefronts.
#define SM_AH 0
#define SM_AL 18432
#define SM_MU 36864
#define SM_INV 37376
#define SM_WS 37888
#define SM_LB 38400
#define SM_ETF 38912
#define SMEM_A_BYTES 39168

__global__ void __launch_bounds__(256, 2)
kernelA(const float* __restrict__ x) {
    extern __shared__ char smc[];
    unsigned sbase = (unsigned)__cvta_generic_to_shared(smc);

    int b = blockIdx.x >> 5;
    int tp = blockIdx.x & 31;
    int t0 = tp * 128;
    int tid = threadIdx.x;
    int lane = tid & 31;
    int warp = tid >> 5;
    int p = tid >> 6;                   // pair id 0..3
    int jg = warp & 1;                  // col half
    int R0 = p * 32;
    int q = tid & 63;
    int fg = (q & 7) * 2;               // float4 col base within 64-d chunk
    int rq = q >> 3;                    // row-in-8 group

    float* mu_s  = reinterpret_cast<float*>(smc + SM_MU);
    float* inv_s = reinterpret_cast<float*>(smc + SM_INV);
    float* ws_s  = reinterpret_cast<float*>(smc + SM_WS);
    float* lb_s  = reinterpret_cast<float*>(smc + SM_LB);
    float* etf_s = reinterpret_cast<float*>(smc + SM_ETF);
    if (tid < 128) {
        ws_s[tid] = g_wsum[tid];
        lb_s[tid] = g_lbsum[tid];
        if (tid < 64) etf_s[tid] = g_exptf[tid];
    }

    // coalesced staging base pointers (row advances by 8 per iter)
    const float* xtb = x + ((size_t)(b * SS) + t0 + R0 + rq) * DD + fg * 4;
    const float* xcb = x + ((size_t)(b * SS) + (t0 ^ SHIFT) + R0 + rq) * DD + fg * 4;
    const float4* g4 = reinterpret_cast<const float4*>(g_gate);

    float st_sum[4], st_sq[4];
#pragma unroll
    for (int i = 0; i < 4; i++) { st_sum[i] = 0.f; st_sq[i] = 0.f; }
    float acc[2][8][4];
#pragma unroll
    for (int i = 0; i < 2; i++)
#pragma unroll
        for (int j = 0; j < 8; j++)
#pragma unroll
            for (int c = 0; c < 4; c++) acc[i][j][c] = 0.f;

    char* ah = smc + SM_AH;
    char* al = smc + SM_AL;

#pragma unroll 1
    for (int ch = 0; ch < 16; ch++) {
        // ---- stage own pair's A rows: blend + stats + fp16 hi/lo split ----
#pragma unroll
        for (int iter = 0; iter < 4; iter++) {
            const float4* pt = reinterpret_cast<const float4*>(xtb + (size_t)iter * 8 * DD + ch * 64);
            const float4* pc = reinterpret_cast<const float4*>(xcb + (size_t)iter * 8 * DD + ch * 64);
            float4 a0 = pt[0], a1 = pt[1];
            float4 c0 = pc[0], c1 = pc[1];
            float4 g0 = __ldg(&g4[ch * 16 + fg]);
            float4 g1 = __ldg(&g4[ch * 16 + fg + 1]);
            float s0 = a0.x + g0.x * (c0.x - a0.x);
            float s1 = a0.y + g0.y * (c0.y - a0.y);
            float s2 = a0.z + g0.z * (c0.z - a0.z);
            float s3 = a0.w + g0.w * (c0.w - a0.w);
            float s4 = a1.x + g1.x * (c1.x - a1.x);
            float s5 = a1.y + g1.y * (c1.y - a1.y);
            float s6 = a1.z + g1.z * (c1.z - a1.z);
            float s7 = a1.w + g1.w * (c1.w - a1.w);
            st_sum[iter] += s0 + s1 + s2 + s3 + s4 + s5 + s6 + s7;
            st_sq[iter]  += s0 * s0 + s1 * s1 + s2 * s2 + s3 * s3
                          + s4 * s4 + s5 * s5 + s6 * s6 + s7 * s7;
            float h0 = h2f(s0), h1 = h2f(s1), h2 = h2f(s2), h3 = h2f(s3);
            float h4 = h2f(s4), h5 = h2f(s5), h6 = h2f(s6), h7 = h2f(s7);
            int rl = R0 + iter * 8 + rq;
            *reinterpret_cast<uint4*>(ah + rl * 144 + fg * 8) =
                make_uint4(packh(h0, h1), packh(h2, h3), packh(h4, h5), packh(h6, h7));
            *reinterpret_cast<uint4*>(al + rl * 144 + fg * 8) =
                make_uint4(packh(s0 - h0, s1 - h1), packh(s2 - h2, s3 - h3),
                           packh(s4 - h4, s5 - h5), packh(s6 - h6, s7 - h7));
        }
        PAIR_BAR(p + 1);   // pair staging visible

        // ---- compute: 4 k16 x (2 m16 x 8 n8) x 2 split-MMAs; B from L2, batched ----
        const uint2* bgl = &g_bfragH[ch * 2048 + (jg * 8) * 32 + lane];
#pragma unroll
        for (int k16 = 0; k16 < 4; k16++) {
            uint2 Bv[8];
#pragma unroll
            for (int j = 0; j < 8; j++) Bv[j] = __ldg(&bgl[(k16 * 16 + j) * 32]);
            unsigned kofs = (unsigned)((k16 * 16 + ((lane & 16) ? 8 : 0)) * 2);
            unsigned a_h[2][4], a_l[2][4];
#pragma unroll
            for (int i = 0; i < 2; i++) {
                unsigned aoff = (unsigned)((R0 + i * 16 + (lane & 15)) * 144) + kofs;
                ldm4(a_h[i], sbase + SM_AH + aoff);
                ldm4(a_l[i], sbase + SM_AL + aoff);
            }
#pragma unroll
            for (int j = 0; j < 8; j++) {
                mma_f16(acc[0][j], a_h[0], Bv[j].x, Bv[j].y);
                mma_f16(acc[0][j], a_l[0], Bv[j].x, Bv[j].y);
                mma_f16(acc[1][j], a_h[1], Bv[j].x, Bv[j].y);
                mma_f16(acc[1][j], a_l[1], Bv[j].x, Bv[j].y);
            }
        }
        PAIR_BAR(p + 1);   // compute done before next overwrite
    }

    // ---- LN stats finalize (8-lane groups share a row) ----
#pragma unroll
    for (int iter = 0; iter < 4; iter++) {
        float s = st_sum[iter], qq = st_sq[iter];
#pragma unroll
        for (int off = 1; off < 8; off <<= 1) {
            s  += __shfl_xor_sync(0xffffffffu, s, off);
            qq += __shfl_xor_sync(0xffffffffu, qq, off);
        }
        if ((q & 7) == 0) {
            int r = R0 + iter * 8 + rq;
            float mu = s * (1.f / DD);
            float var = qq * (1.f / DD) - mu * mu;
            mu_s[r] = mu;
            inv_s[r] = rsqrtf(var + 1e-5f);
        }
    }
    __syncthreads();

    // ---- epilogue: LN fold + wkv -> smem (overlay A region, pitch 68) ----
    float* wkv_s = reinterpret_cast<float*>(smc);
    int tr = lane >> 2, tc = lane & 3;
#pragma unroll
    for (int i = 0; i < 2; i++) {
#pragma unroll
        for (int j = 0; j < 8; j++) {
            int n = (jg * 8 + j) * 4 + tc;
            int o0 = 2 * n;
            float etf = etf_s[n];
            float wsk = ws_s[o0], wsv = ws_s[o0 + 1];
            float lbk = lb_s[o0], lbv = lb_s[o0 + 1];
#pragma unroll
            for (int h = 0; h < 2; h++) {
                int r = R0 + i * 16 + tr + h * 8;
                float mu = mu_s[r], inv = inv_s[r];
                float k = inv * (acc[i][j][2 * h] - mu * wsk) + lbk;
                float v = inv * (acc[i][j][2 * h + 1] - mu * wsv) + lbv;
                wkv_s[r * 68 + n] = expf(-etf * k) * v;
            }
        }
    }
    __syncthreads();

    // ---- coalesced g_wkv store ----
    {
        int rr = tid >> 1;
        int seg = tid & 1;
        float* dst = &g_wkv[((size_t)(b * SS) + t0 + rr) * NN + seg * 32];
        const float* src = &wkv_s[rr * 68 + seg * 32];
#pragma unroll
        for (int k4 = 0; k4 < 8; k4++)
            reinterpret_cast<float4*>(dst)[k4] = *reinterpret_cast<const float4*>(src + 4 * k4);
    }
    // ---- chunk sums (4 sub-chunks of 32 rows) ----
    {
        int sub = tid >> 6;
        int n = tid & 63;
        float w = g_w[n];
        float a = 0.f;
#pragma unroll
        for (int r2 = 0; r2 < 32; r2++) a = a * w + wkv_s[(sub * 32 + r2) * 68 + n];
        g_chunk[((size_t)b * NCH + tp * 4 + sub) * NN + n] = a;
    }
}

// ---------------- carry prefix over chunks ----------------
__global__ void scan_carry(const float* __restrict__ td, float* __restrict__ lastout,
                           int write_last) {
    int tid = threadIdx.x;
    int n = tid & (NN - 1);
    int b = tid >> 6;
    float wL = expf((float)CHL * td[n]);
    float carry = 0.f;
    for (int c0 = 0; c0 < NCH; c0 += 8) {
        float v[8];
#pragma unroll
        for (int i = 0; i < 8; i++) v[i] = g_chunk[((size_t)b * NCH + c0 + i) * NN + n];
#pragma unroll
        for (int i = 0; i < 8; i++) {
            g_carry[((size_t)b * NCH + c0 + i) * NN + n] = carry;
            carry = carry * wL + v[i];
        }
    }
    if (write_last) lastout[b * NN + n] = carry;
}

// ---------------- kernel C: fused scan + HMMA output projection ----------------
__global__ void __launch_bounds__(256)
kernelC(float* __restrict__ out) {
    __shared__ float wk[TILE_C * NN];       // 8KB
    __shared__ float sT[NN * 36];           // 9KB
    __shared__ char cA[2][32 * 144];        // fp16 hi/lo state tiles

    int b = blockIdx.x >> 7;
    int c = blockIdx.x & 127;
    int t0 = c * TILE_C;
    int tid = threadIdx.x;
    int lane = tid & 31;
    int warp = tid >> 5;

    {
        const float4* src = reinterpret_cast<const float4*>(&g_wkv[((size_t)(b * SS) + t0) * NN]);
        float4* dst = reinterpret_cast<float4*>(wk);
        dst[tid] = src[tid];
        dst[256 + tid] = src[256 + tid];
    }
    __syncthreads();

    if (tid < NN) {
        int n = tid;
        float w = g_w[n];
        float st = g_carry[((size_t)b * NCH + c) * NN + n];
#pragma unroll
        for (int r = 0; r < TILE_C; r++) {
            st = st * w + wk[r * NN + n];
            sT[n * 36 + r] = st;
        }
    }
    __syncthreads();

    {
        int r = tid >> 3;
        int seg = tid & 7;
        float v[8];
#pragma unroll
        for (int j = 0; j < 8; j++) v[j] = sT[(seg * 8 + j) * 36 + r];
        unsigned hp[4], lp[4];
#pragma unroll
        for (int e = 0; e < 4; e++) {
            float a = v[2 * e], bb = v[2 * e + 1];
            float ha = h2f(a), hb = h2f(bb);
            hp[e] = packh(ha, hb);
            lp[e] = packh(a - ha, bb - hb);
        }
        *reinterpret_cast<uint4*>(&cA[0][r * 144 + seg * 16]) = make_uint4(hp[0], hp[1], hp[2], hp[3]);
        *reinterpret_cast<uint4*>(&cA[1][r * 144 + seg * 16]) = make_uint4(lp[0], lp[1], lp[2], lp[3]);
    }
    __syncthreads();

    int mi = warp >> 2;
    int nq = warp & 3;
    unsigned sbase0 = (unsigned)__cvta_generic_to_shared(&cA[0][0]);
    unsigned sbase1 = (unsigned)__cvta_generic_to_shared(&cA[1][0]);
    unsigned a_h[4][4], a_l[4][4];
#pragma unroll
    for (int k16 = 0; k16 < 4; k16++) {
        unsigned aoff = (unsigned)((mi * 16 + (lane & 15)) * 144 + (k16 * 16 + ((lane & 16) ? 8 : 0)) * 2);
        ldm4(a_h[k16], sbase0 + aoff);
        ldm4(a_l[k16], sbase1 + aoff);
    }

    int tr = lane >> 2, tc = lane & 3;
    float* ob = out + ((size_t)(b * SS) + t0 + mi * 16) * DD;
#pragma unroll 2
    for (int j0 = 0; j0 < 32; j0++) {
        int j = nq * 32 + j0;
        uint2 BH[4], BL[4];
#pragma unroll
        for (int k16 = 0; k16 < 4; k16++) {
            BH[k16] = __ldg(&g_owfH[(k16 * 128 + j) * 32 + lane]);
            BL[k16] = __ldg(&g_owfL[(k16 * 128 + j) * 32 + lane]);
        }
        float accA[4] = {0.f, 0.f, 0.f, 0.f};
        float accB[4] = {0.f, 0.f, 0.f, 0.f};
#pragma unroll
        for (int k16 = 0; k16 < 4; k16++) {
            mma_f16(accA, a_h[k16], BH[k16].x, BH[k16].y);
            mma_f16(accB, a_l[k16], BH[k16].x, BH[k16].y);
            mma_f16(accB, a_h[k16], BL[k16].x, BL[k16].y);
        }
        int d = j * 8 + tc * 2;
        *reinterpret_cast<float2*>(&ob[(size_t)tr * DD + d]) =
            make_float2(accA[0] + accB[0], accA[1] + accB[1]);
        *reinterpret_cast<float2*>(&ob[(size_t)(tr + 8) * DD + d]) =
            make_float2(accA[2] + accB[2], accA[3] + accB[3]);
    }
}

// ---------------- launch ----------------
extern "C" void kernel_launch(void* const* d_in, const int* in_sizes, int n_in,
                              void* d_out, int out_size) {
    const float* x   = (const float*)d_in[0];
    const float* td  = (const float*)d_in[1];
    const float* tf  = (const float*)d_in[2];
    const float* kw  = (const float*)d_in[3];
    const float* vw  = (const float*)d_in[4];
    const float* ow  = (const float*)d_in[5];
    const float* tsg = (const float*)d_in[6];
    const float* lnw = (const float*)d_in[7];
    const float* lnb = (const float*)d_in[8];
    float* out = (float*)d_out;

    cudaFuncSetAttribute(kernelA, cudaFuncAttributeMaxDynamicSharedMemorySize, SMEM_A_BYTES);

    prep_a<<<(DD * 128) / 256, 256>>>(kw, vw, lnw, tsg, td, tf);
    prep_frag<<<128, 256>>>(ow);
    prep_b<<<128, 256>>>(kw, vw, lnb);
    kernelA<<<BB * 32, 256, SMEM_A_BYTES>>>(x);
    int write_last = (out_size >= BB * SS * DD + BB * NN) ? 1 : 0;
    scan_carry<<<1, 512>>>(td, out + (size_t)BB * SS * DD, write_last);
    kernelC<<<BB * (SS / TILE_C), 256>>>(out);
}